// round 16
// baseline (speedup 1.0000x reference)
#include <cuda_runtime.h>
#include <math.h>
#include <stdint.h>

#define NB 4
#define NS 2048
#define ND 1024
#define NH 16
#define NDK 10
#define NDV 12
#define DP 12
#define NROW (NB*NS)          // 8192
#define NCOL (NH*DP)          // 192
#define KCELL 20              // 2 keys x 10 dims, pair-interleaved
#define NFQ 98304             // per-z QKV B-plane u32 count = 64kt*24nt*64
#define NFO 98304             // WO plane u32 count = 12kt*128nt*64

// scratch (device globals: no allocation allowed)
__device__ unsigned int g_bh[3*NFQ];         // QKV weights bf16-hi frag planes (Q scale folded)
__device__ unsigned int g_bl[3*NFQ];         // lo planes
__device__ unsigned int g_woh[NFO];          // WO bf16-hi frag plane
__device__ unsigned int g_wol[NFO];          // WO lo plane
__device__ float g_qp[NB*NH*NS*DP];          // q*(log2e/sqrt10), 12-stride, cols 0..9 valid
__device__ float g_ki[NB*NH*(NS/2)*KCELL];   // K pairs: cell[j] = (k_{2t}[j], k_{2t+1}[j])
__device__ float g_vp[NB*NH*NS*DP];          // v, straight 12-stride rows
__device__ float g_heads[NROW*NCOL];         // concat heads [b*S+s][h*12+j]

typedef unsigned long long u64;
typedef unsigned int u32;

__device__ __forceinline__ u64 ffma2(u64 a, u64 b, u64 c) {
    u64 d; asm("fma.rn.f32x2 %0, %1, %2, %3;" : "=l"(d) : "l"(a), "l"(b), "l"(c)); return d;
}
__device__ __forceinline__ u64 fadd2(u64 a, u64 b) {
    u64 d; asm("add.rn.f32x2 %0, %1, %2;" : "=l"(d) : "l"(a), "l"(b)); return d;
}
__device__ __forceinline__ u64 pack2(float x, float y) {
    u64 r; asm("mov.b64 %0, {%1, %2};" : "=l"(r) : "f"(x), "f"(y)); return r;
}
__device__ __forceinline__ void unpack2(u64 v, float& x, float& y) {
    asm("mov.b64 {%0, %1}, %2;" : "=f"(x), "=f"(y) : "l"(v));
}
__device__ __forceinline__ float ex2f(float x) {
    float y; asm("ex2.approx.f32 %0, %1;" : "=f"(y) : "f"(x)); return y;
}
// cvt.rn.bf16x2.f32 d, a, b -> upper16 = bf16(a), lower16 = bf16(b)
__device__ __forceinline__ u32 cvt_bf16x2(float hi, float lo) {
    u32 r; asm("cvt.rn.bf16x2.f32 %0, %1, %2;" : "=r"(r) : "f"(hi), "f"(lo)); return r;
}
// split fp32 pair (x0 -> low half, x1 -> high half) into bf16 hi/lo packed u32s
__device__ __forceinline__ void split2(float x0, float x1, u32& hi, u32& lo) {
    hi = cvt_bf16x2(x1, x0);
    float h0 = __uint_as_float(hi << 16);
    float h1 = __uint_as_float(hi & 0xFFFF0000u);
    lo = cvt_bf16x2(x1 - h1, x0 - h0);
}
__device__ __forceinline__ void mma_bf16(float* c, const u32* a, u32 b0, u32 b1) {
    asm volatile(
        "mma.sync.aligned.m16n8k16.row.col.f32.bf16.bf16.f32 "
        "{%0,%1,%2,%3}, {%4,%5,%6,%7}, {%8,%9}, {%0,%1,%2,%3};"
        : "+f"(c[0]), "+f"(c[1]), "+f"(c[2]), "+f"(c[3])
        : "r"(a[0]), "r"(a[1]), "r"(a[2]), "r"(a[3]), "r"(b0), "r"(b1));
}

// ---------------------------------------------------------------------------
// Kernel 0a: QKV weights -> bf16 hi/lo m16n8k16 B-fragment planes.
// ---------------------------------------------------------------------------
__global__ __launch_bounds__(256) void prep_qkv_kernel(
    const float* __restrict__ WQ, const float* __restrict__ WK, const float* __restrict__ WV)
{
    int idx = blockIdx.x * 256 + threadIdx.x;     // < 3*512*192
    int z = idx / (512 * NCOL);
    int rem = idx - z * 512 * NCOL;
    int k2 = rem / NCOL, n = rem - k2 * NCOL;
    int h = n / DP, j = n - h * DP;
    const float* W = (z == 0) ? WQ : ((z == 1) ? WK : WV);
    int dout = (z == 2) ? NDV : NDK;
    float w0 = 0.0f, w1 = 0.0f;
    if (j < dout) {
        w0 = W[(h * ND + 2 * k2) * dout + j];
        w1 = W[(h * ND + 2 * k2 + 1) * dout + j];
    }
    if (z == 0) {
        const float sc = 1.4426950408889634f * rsqrtf(10.0f);
        w0 *= sc; w1 *= sc;
    }
    u32 hi, lo;
    split2(w0, w1, hi, lo);
    int kt = k2 >> 3, r = (k2 >> 2) & 1, p = k2 & 3;
    int nt = n >> 3, nr = n & 7;
    int addr = z * NFQ + kt * 1536 + nt * 64 + r * 32 + nr * 4 + p;
    g_bh[addr] = hi;
    g_bl[addr] = lo;
}

// ---------------------------------------------------------------------------
// Kernel 0b: WO -> bf16 hi/lo fragment planes. WO is [192, 1024].
// ---------------------------------------------------------------------------
__global__ __launch_bounds__(256) void prep_wo_kernel(const float* __restrict__ WO)
{
    int idx = blockIdx.x * 256 + threadIdx.x;     // < 96*1024
    int k2 = idx / ND, n = idx - k2 * ND;
    float w0 = WO[(2 * k2) * ND + n];
    float w1 = WO[(2 * k2 + 1) * ND + n];
    u32 hi, lo;
    split2(w0, w1, hi, lo);
    int kt = k2 >> 3, r = (k2 >> 2) & 1, p = k2 & 3;
    int nt = n >> 3, nr = n & 7;
    int addr = kt * 8192 + nt * 64 + r * 32 + nr * 4 + p;
    g_woh[addr] = hi;
    g_wol[addr] = lo;
}

// ---------------------------------------------------------------------------
// Kernel 1: QKV projection via bf16 m16n8k16 mma.sync, 3-way split.
// (verbatim from R15 best)
// ---------------------------------------------------------------------------
#define PROJ_SMEM (128*196*4)   // 100352 B; A planes (20480 B) alias low part

__global__ __launch_bounds__(256) void proj_mma_kernel(
    const float* __restrict__ Q, const float* __restrict__ K, const float* __restrict__ V)
{
    extern __shared__ char smraw[];
    u32* AH = (u32*)smraw;              // [128][20]
    u32* AL = AH + 128 * 20;            // [128][20]
    float* Cs = (float*)smraw;          // [128][196] during epilogue

    const int z = blockIdx.z;
    const float* X = (z == 0) ? Q : ((z == 1) ? K : V);
    const u32* Bhi = g_bh + (size_t)z * NFQ;
    const u32* Blo = g_bl + (size_t)z * NFQ;

    const int tid = threadIdx.x;
    const int warp = tid >> 5, lane = tid & 31;
    const int wm = warp & 1, wn = warp >> 1;      // 2m x 4n
    const int g = lane >> 2, tig = lane & 3;
    const int row0 = blockIdx.x * 128;

    float acc[4][6][4];
    #pragma unroll
    for (int mt = 0; mt < 4; mt++)
        #pragma unroll
        for (int nt = 0; nt < 6; nt++)
            #pragma unroll
            for (int c = 0; c < 4; c++) acc[mt][nt][c] = 0.0f;

    for (int t = 0; t < ND / 32; t++) {
        #pragma unroll
        for (int i = 0; i < 4; i++) {
            int f = tid + i * 256;
            int row = f >> 3, seg = f & 7;
            float4 v = *(const float4*)(X + (size_t)(row0 + row) * ND + t * 32 + seg * 4);
            u32 h01, l01, h23, l23;
            split2(v.x, v.y, h01, l01);
            split2(v.z, v.w, h23, l23);
            *(uint2*)&AH[row * 20 + seg * 2] = make_uint2(h01, h23);
            *(uint2*)&AL[row * 20 + seg * 2] = make_uint2(l01, l23);
        }
        __syncthreads();

        #pragma unroll
        for (int ks = 0; ks < 2; ks++) {
            const int kt = t * 2 + ks;
            u32 ah[4][4], al[4][4];
            #pragma unroll
            for (int mt = 0; mt < 4; mt++) {
                int r0w = (wm * 64 + mt * 16 + g) * 20 + ks * 8 + tig;
                int r1w = r0w + 8 * 20;
                ah[mt][0] = AH[r0w];     ah[mt][1] = AH[r1w];
                ah[mt][2] = AH[r0w + 4]; ah[mt][3] = AH[r1w + 4];
                al[mt][0] = AL[r0w];     al[mt][1] = AL[r1w];
                al[mt][2] = AL[r0w + 4]; al[mt][3] = AL[r1w + 4];
            }
            const u32* bh = Bhi + kt * 1536 + (wn * 6) * 64 + lane;
            const u32* bl = Blo + kt * 1536 + (wn * 6) * 64 + lane;
            #pragma unroll
            for (int nt = 0; nt < 6; nt++) {
                u32 b0h = bh[nt * 64], b1h = bh[nt * 64 + 32];
                u32 b0l = bl[nt * 64], b1l = bl[nt * 64 + 32];
                #pragma unroll
                for (int mt = 0; mt < 4; mt++) {
                    mma_bf16(acc[mt][nt], ah[mt], b0h, b1h);
                    mma_bf16(acc[mt][nt], ah[mt], b0l, b1l);
                    mma_bf16(acc[mt][nt], al[mt], b0h, b1h);
                }
            }
        }
        __syncthreads();
    }

    // ---- epilogue: fragments -> Cs ----
    #pragma unroll
    for (int mt = 0; mt < 4; mt++)
        #pragma unroll
        for (int nt = 0; nt < 6; nt++) {
            int row = wm * 64 + mt * 16 + g;
            int col = wn * 48 + nt * 8 + 2 * tig;
            float* c = acc[mt][nt];
            *(float2*)&Cs[row * 196 + col]       = make_float2(c[0], c[1]);
            *(float2*)&Cs[(row + 8) * 196 + col] = make_float2(c[2], c[3]);
        }
    __syncthreads();

    // ---- Cs -> global (proven layouts) ----
    if (z == 1) {       // K: pair-interleaved cells, dims 0..9
        const int p = tid >> 2, tq = tid & 3;
        const int grow0 = row0 + 2 * p;
        const int b = grow0 >> 11;
        const int s2 = ((grow0 & 2047) >> 1);
        const float* r0 = &Cs[(2 * p) * 196];
        const float* r1 = &Cs[(2 * p + 1) * 196];
        #pragma unroll
        for (int hh = 0; hh < 4; hh++) {
            const int h = tq * 4 + hh;
            u64* cell = (u64*)(g_ki + ((size_t)(b * NH + h) * (NS / 2) + s2) * KCELL);
            #pragma unroll
            for (int j = 0; j < 10; j += 2) {
                ulonglong2 v;
                v.x = pack2(r0[h * 12 + j],     r1[h * 12 + j]);
                v.y = pack2(r0[h * 12 + j + 1], r1[h * 12 + j + 1]);
                *(ulonglong2*)(cell + j) = v;
            }
        }
    } else {            // Q / V: straight 12-stride rows
        const int row = tid >> 1, half = tid & 1;
        const int grow = row0 + row;
        const int b = grow >> 11, s = grow & 2047;
        const float* src = &Cs[row * 196];
        float* base = (z == 0) ? g_qp : g_vp;
        #pragma unroll
        for (int hh = 0; hh < 8; hh++) {
            const int h = half * 8 + hh;
            const float* fs = src + h * 12;
            float* dst = base + ((size_t)(b * NH + h) * NS + s) * DP;
            *(float4*)(dst + 0) = make_float4(fs[0], fs[1], fs[2], fs[3]);
            *(float4*)(dst + 4) = make_float4(fs[4], fs[5], fs[6], fs[7]);
            if (z == 0) *(float2*)(dst + 8) = make_float2(fs[8], fs[9]);
            else        *(float4*)(dst + 8) = make_float4(fs[8], fs[9], fs[10], fs[11]);
        }
    }
}

// ---------------------------------------------------------------------------
// Kernel 2: attention v2 — occupancy fix. grid (2, 64), 1024 threads,
// ONE q-row per thread (regs <= 64 -> 32 warps/SM = 8 warps/SMSP).
// K (80KB pair-interleaved) + V (96KB straight) resident in smem.
// Same no-max base-2 softmax inner math as the proven kernel.
// ---------------------------------------------------------------------------
__global__ __launch_bounds__(1024, 1) void attn_kernel()
{
    extern __shared__ float smem[];
    float* ksf = smem;                     // [1024 cells][20]
    float* vs  = smem + 1024 * KCELL;      // [2048][12]
    const int bh = blockIdx.y;
    const int tid = threadIdx.x;

    {
        const float4* src = (const float4*)(g_ki + (size_t)bh * (NS / 2) * KCELL);
        float4* dst = (float4*)ksf;
        for (int i = tid; i < NS / 2 * KCELL / 4; i += 1024) dst[i] = src[i];
        const float4* vsrc = (const float4*)(g_vp + (size_t)bh * NS * DP);
        float4* vdst = (float4*)vs;
        for (int i = tid; i < NS * DP / 4; i += 1024) vdst[i] = vsrc[i];
    }
    __syncthreads();

    const int row = blockIdx.x * 1024 + tid;

    u64 q2[10];
    {
        const float* qr = g_qp + ((size_t)bh * NS + row) * DP;
        float4 a = *(const float4*)qr, bq = *(const float4*)(qr + 4);
        float2 c = *(const float2*)(qr + 8);
        float q[10] = { a.x, a.y, a.z, a.w, bq.x, bq.y, bq.z, bq.w, c.x, c.y };
        #pragma unroll
        for (int i = 0; i < 10; i++) q2[i] = pack2(q[i], q[i]);
    }

    float l = 0.0f;
    u64 acc[6] = {0ull, 0ull, 0ull, 0ull, 0ull, 0ull};
    const ulonglong2* ks2 = (const ulonglong2*)ksf;

    for (int t2 = 0; t2 < NS / 2; t2++) {
        ulonglong2 k0 = ks2[(size_t)t2 * 5 + 0];
        ulonglong2 k1 = ks2[(size_t)t2 * 5 + 1];
        ulonglong2 k2 = ks2[(size_t)t2 * 5 + 2];
        ulonglong2 k3 = ks2[(size_t)t2 * 5 + 3];
        ulonglong2 k4 = ks2[(size_t)t2 * 5 + 4];

        u64 s1 = 0ull, s2 = 0ull;          // two 5-deep chains
        s1 = ffma2(q2[0], k0.x, s1);  s2 = ffma2(q2[1], k0.y, s2);
        s1 = ffma2(q2[2], k1.x, s1);  s2 = ffma2(q2[3], k1.y, s2);
        s1 = ffma2(q2[4], k2.x, s1);  s2 = ffma2(q2[5], k2.y, s2);
        s1 = ffma2(q2[6], k3.x, s1);  s2 = ffma2(q2[7], k3.y, s2);
        s1 = ffma2(q2[8], k4.x, s1);  s2 = ffma2(q2[9], k4.y, s2);

        float s0f, s1f;
        unpack2(fadd2(s1, s2), s0f, s1f);
        float p0 = ex2f(s0f), p1 = ex2f(s1f);
        l += p0 + p1;
        u64 pp0 = pack2(p0, p0), pp1 = pack2(p1, p1);

        const ulonglong2* vp2 = (const ulonglong2*)(vs + (size_t)(2 * t2) * DP);
        ulonglong2 va = vp2[0], vb = vp2[1], vc = vp2[2];
        acc[0] = ffma2(pp0, va.x, acc[0]);
        acc[1] = ffma2(pp0, va.y, acc[1]);
        acc[2] = ffma2(pp0, vb.x, acc[2]);
        acc[3] = ffma2(pp0, vb.y, acc[3]);
        acc[4] = ffma2(pp0, vc.x, acc[4]);
        acc[5] = ffma2(pp0, vc.y, acc[5]);
        ulonglong2 vd = vp2[3], ve = vp2[4], vf = vp2[5];
        acc[0] = ffma2(pp1, vd.x, acc[0]);
        acc[1] = ffma2(pp1, vd.y, acc[1]);
        acc[2] = ffma2(pp1, ve.x, acc[2]);
        acc[3] = ffma2(pp1, ve.y, acc[3]);
        acc[4] = ffma2(pp1, vf.x, acc[4]);
        acc[5] = ffma2(pp1, vf.y, acc[5]);
    }

    const int b = bh >> 4, h = bh & 15;
    float inv = 1.0f / l;
    float o[12];
    #pragma unroll
    for (int j = 0; j < 6; j++) unpack2(acc[j], o[2 * j], o[2 * j + 1]);
    float* dst = g_heads + (size_t)(b * NS + row) * NCOL + h * NDV;
    *(float4*)(dst + 0) = make_float4(o[0] * inv, o[1] * inv, o[2]  * inv, o[3]  * inv);
    *(float4*)(dst + 4) = make_float4(o[4] * inv, o[5] * inv, o[6]  * inv, o[7]  * inv);
    *(float4*)(dst + 8) = make_float4(o[8] * inv, o[9] * inv, o[10] * inv, o[11] * inv);
}

// ---------------------------------------------------------------------------
// Kernel 3: output projection via bf16 m16n8k16 mma.sync (verbatim R15).
// ---------------------------------------------------------------------------
#define OUT_SMEM (128*20*4*2)    // 20480 B (bf16 hi/lo A planes)

__global__ __launch_bounds__(256) void outproj_mma_kernel(float* __restrict__ out)
{
    extern __shared__ char smraw[];
    u32* AH = (u32*)smraw;
    u32* AL = AH + 128 * 20;

    const int tid = threadIdx.x;
    const int warp = tid >> 5, lane = tid & 31;
    const int wm = warp & 1, wn = warp >> 1;
    const int g = lane >> 2, tig = lane & 3;
    const int row0 = blockIdx.y * 128;
    const int col0 = blockIdx.x * 128;

    float acc[4][4][4];
    #pragma unroll
    for (int mt = 0; mt < 4; mt++)
        #pragma unroll
        for (int nt = 0; nt < 4; nt++)
            #pragma unroll
            for (int c = 0; c < 4; c++) acc[mt][nt][c] = 0.0f;

    for (int t = 0; t < NCOL / 32; t++) {
        #pragma unroll
        for (int i = 0; i < 4; i++) {
            int f = tid + i * 256;
            int row = f >> 3, seg = f & 7;
            float4 v = *(const float4*)(g_heads + (size_t)(row0 + row) * NCOL + t * 32 + seg * 4);
            u32 h01, l01, h23, l23;
            split2(v.x, v.y, h01, l01);
            split2(v.z, v.w, h23, l23);
            *(uint2*)&AH[row * 20 + seg * 2] = make_uint2(h01, h23);
            *(uint2*)&AL[row * 20 + seg * 2] = make_uint2(l01, l23);
        }
        __syncthreads();

        #pragma unroll
        for (int ks = 0; ks < 2; ks++) {
            const int kt = t * 2 + ks;
            u32 ah[4][4], al[4][4];
            #pragma unroll
            for (int mt = 0; mt < 4; mt++) {
                int r0w = (wm * 64 + mt * 16 + g) * 20 + ks * 8 + tig;
                int r1w = r0w + 8 * 20;
                ah[mt][0] = AH[r0w];     ah[mt][1] = AH[r1w];
                ah[mt][2] = AH[r0w + 4]; ah[mt][3] = AH[r1w + 4];
                al[mt][0] = AL[r0w];     al[mt][1] = AL[r1w];
                al[mt][2] = AL[r0w + 4]; al[mt][3] = AL[r1w + 4];
            }
            const int gnt0 = (col0 >> 3) + wn * 4;
            const u32* bh = g_woh + kt * 8192 + gnt0 * 64 + lane;
            const u32* bl = g_wol + kt * 8192 + gnt0 * 64 + lane;
            #pragma unroll
            for (int nt = 0; nt < 4; nt++) {
                u32 b0h = bh[nt * 64], b1h = bh[nt * 64 + 32];
                u32 b0l = bl[nt * 64], b1l = bl[nt * 64 + 32];
                #pragma unroll
                for (int mt = 0; mt < 4; mt++) {
                    mma_bf16(acc[mt][nt], ah[mt], b0h, b1h);
                    mma_bf16(acc[mt][nt], ah[mt], b0l, b1l);
                    mma_bf16(acc[mt][nt], al[mt], b0h, b1h);
                }
            }
        }
        __syncthreads();
    }

    // direct epilogue
    #pragma unroll
    for (int mt = 0; mt < 4; mt++)
        #pragma unroll
        for (int nt = 0; nt < 4; nt++) {
            int row = row0 + wm * 64 + mt * 16 + g;
            int col = col0 + wn * 32 + nt * 8 + 2 * tig;
            float* c = acc[mt][nt];
            *(float2*)&out[(size_t)row * ND + col]       = make_float2(c[0], c[1]);
            *(float2*)&out[(size_t)(row + 8) * ND + col] = make_float2(c[2], c[3]);
        }
}

// ---------------------------------------------------------------------------
extern "C" void kernel_launch(void* const* d_in, const int* in_sizes, int n_in,
                              void* d_out, int out_size)
{
    const float* Q  = (const float*)d_in[0];
    const float* K  = (const float*)d_in[1];
    const float* V  = (const float*)d_in[2];
    const float* WQ = (const float*)d_in[3];
    const float* WK = (const float*)d_in[4];
    const float* WV = (const float*)d_in[5];
    const float* WO = (const float*)d_in[6];
    float* out = (float*)d_out;

    const int attn_smem = (1024 * KCELL + NS * DP) * 4;   // 80KB + 96KB = 176KB
    cudaFuncSetAttribute(attn_kernel, cudaFuncAttributeMaxDynamicSharedMemorySize, attn_smem);
    cudaFuncSetAttribute(proj_mma_kernel, cudaFuncAttributeMaxDynamicSharedMemorySize, PROJ_SMEM);
    cudaFuncSetAttribute(outproj_mma_kernel, cudaFuncAttributeMaxDynamicSharedMemorySize, OUT_SMEM);

    prep_qkv_kernel<<<3 * 512 * NCOL / 256, 256>>>(WQ, WK, WV);
    prep_wo_kernel<<<96 * ND / 256, 256>>>(WO);

    dim3 g1(NROW / 128, 1, 3);
    proj_mma_kernel<<<g1, 256, PROJ_SMEM>>>(Q, K, V);

    dim3 g2(NS / 1024, NB * NH);
    attn_kernel<<<g2, 1024, attn_smem>>>();

    dim3 g3(ND / 128, NROW / 128);
    outproj_mma_kernel<<<g3, 256, OUT_SMEM>>>(out);
}